// round 6
// baseline (speedup 1.0000x reference)
#include <cuda_runtime.h>
#include <cuda_bf16.h>

// Problem constants
#define BATCH 64
#define SEQ   1024
#define DIN   256
#define UNITS 512

// Recurrence partitioning: 16 batch-groups x 8 unit-slices = 128 CTAs.
// One group == one 8-CTA cluster (portable size) -> HW cluster barrier sync.
#define NGRP   16     // batch groups (4 rows each)
#define GROWS  4      // batch rows per group
#define NSLICE 8      // unit slices per group (cluster size)
#define SU     64     // units per slice
#define KDIM   512    // contraction dim (= UNITS)
#define UPAD   516    // padded k-row length for U in smem (conflict-free LDS.128)

typedef unsigned long long ull;

// Double-buffered hidden state, stored TRANSPOSED per group: [buf][g][k][r]
__device__ float g_hbuf_t[2][NGRP][KDIM][GROWS];   // 2*16*512*4 floats = 256 KB

// ---------------------------------------------------------------------------
// f32x2 packed helpers (sm_103a FFMA2 path — only reachable via PTX)
// ---------------------------------------------------------------------------
__device__ __forceinline__ ull pack2(float v) {
    ull d;
    asm("mov.b64 %0, {%1, %1};" : "=l"(d) : "f"(v));
    return d;
}
__device__ __forceinline__ ull fma2(ull a, ull b, ull c) {
    ull d;
    asm("fma.rn.f32x2 %0, %1, %2, %3;" : "=l"(d) : "l"(a), "l"(b), "l"(c));
    return d;
}
__device__ __forceinline__ ull add2(ull a, ull b) {
    ull d;
    asm("add.rn.f32x2 %0, %1, %2;" : "=l"(d) : "l"(a), "l"(b));
    return d;
}

// ---------------------------------------------------------------------------
// Kernel 1: xW GEMM  C[65536,512] = A[65536,256] @ B[256,512], written to out.
// ---------------------------------------------------------------------------
#define BM 128
#define BN 128
#define BK 8

__global__ __launch_bounds__(256) void ltc_xw_gemm(
    const float* __restrict__ A,   // [65536, 256]
    const float* __restrict__ B,   // [256, 512]
    float* __restrict__ C)         // [65536, 512]
{
    __shared__ float Asm[BK][BM];
    __shared__ float Bsm[BK][BN];

    const int tid = threadIdx.x;
    const int bm = blockIdx.y * BM;
    const int bn = blockIdx.x * BN;

    const int tx = tid & 15;
    const int ty = tid >> 4;

    const int arow = tid >> 1;
    const int acol = (tid & 1) * 4;
    const int brow = tid >> 5;
    const int bcol = (tid & 31) * 4;

    const float* Ap = A + (long)(bm + arow) * DIN + acol;
    const float* Bp = B + (long)brow * UNITS + bn + bcol;

    float acc[8][8];
#pragma unroll
    for (int i = 0; i < 8; i++)
#pragma unroll
        for (int j = 0; j < 8; j++) acc[i][j] = 0.0f;

    for (int k0 = 0; k0 < DIN; k0 += BK) {
        float4 av = *(const float4*)(Ap + k0);
        float4 bv = *(const float4*)(Bp + (long)k0 * UNITS);

        __syncthreads();
        Asm[acol + 0][arow] = av.x;
        Asm[acol + 1][arow] = av.y;
        Asm[acol + 2][arow] = av.z;
        Asm[acol + 3][arow] = av.w;
        *(float4*)&Bsm[brow][bcol] = bv;
        __syncthreads();

#pragma unroll
        for (int k = 0; k < BK; ++k) {
            float a[8], b[8];
            *(float4*)(a)     = *(const float4*)&Asm[k][ty * 8];
            *(float4*)(a + 4) = *(const float4*)&Asm[k][ty * 8 + 4];
            *(float4*)(b)     = *(const float4*)&Bsm[k][tx * 8];
            *(float4*)(b + 4) = *(const float4*)&Bsm[k][tx * 8 + 4];
#pragma unroll
            for (int i = 0; i < 8; i++)
#pragma unroll
                for (int j = 0; j < 8; j++)
                    acc[i][j] = fmaf(a[i], b[j], acc[i][j]);
        }
    }

#pragma unroll
    for (int i = 0; i < 8; i++) {
        float* crow = C + (long)(bm + ty * 8 + i) * UNITS + bn + tx * 8;
        *(float4*)(crow)     = make_float4(acc[i][0], acc[i][1], acc[i][2], acc[i][3]);
        *(float4*)(crow + 4) = make_float4(acc[i][4], acc[i][5], acc[i][6], acc[i][7]);
    }
}

// ---------------------------------------------------------------------------
// Kernel 2: persistent LTC recurrence (cluster-synced, f32x2 packed math).
//
// Grid = 128 CTAs, __cluster_dims__(8): blockIdx.x = g*8 + s.
// Cluster g owns batch rows [4g, 4g+4); CTA s owns units [64s, 64s+64).
// Smem (per CTA, resident for the whole run):
//   Usm_t [64][516]  : U[:, slice] transposed (u-major), 129 KB
//   hsm_t [512][4]   : full h_{t-1} for this group's 4 rows, row-transposed, 8 KB
//   red   [4][64][2] : f32x2 k-group partials, 4 KB
// Per step t:
//   compute: thread (u = tid&63, kg = tid>>6) accumulates k in [128kg,128kg+128)
//            with fma.rn.f32x2 over row-pairs (0,1),(2,3); U via LDS.128,
//            h row-quad via one LDS.128 (broadcast) = two packed operands free.
//   combine: thread (r = tid>>6, u = tid&63) sums 4 partials, applies the LTC
//            update with prefetched xw, writes out + g_hbuf_t[(t+1)&1].
//   sync:    one barrier.cluster (release/acquire) + h reload from L2.
// xw[t] is prefetched one step ahead (__ldcg) so DRAM latency hides behind
// the barrier + compute of the previous step.
// ---------------------------------------------------------------------------
#define REC_THREADS 256
#define SMEM_U_FLOATS (SU * UPAD)          // 33024
#define SMEM_H_FLOATS (KDIM * GROWS)       // 2048
#define SMEM_R_FLOATS (4 * SU * 2 * 2)     // 1024  (4 kg x 64 u x 2 pairs, f32x2)
#define SMEM_FLOATS   (SMEM_U_FLOATS + SMEM_H_FLOATS + SMEM_R_FLOATS + 2 * SU)
#define SMEM_BYTES    (SMEM_FLOATS * 4)

extern __shared__ float s_mem[];

__global__ __launch_bounds__(REC_THREADS, 1) __cluster_dims__(NSLICE, 1, 1)
void ltc_recur(
    const float* __restrict__ Umat,  // [512, 512] row-major [k][u]
    const float* __restrict__ bvec,  // [512]
    const float* __restrict__ tau,   // [512]
    float* __restrict__ out)         // [64, 1024, 512]; holds xW on entry
{
    float* Usm  = s_mem;                      // [u][k] padded: u*UPAD + k
    float* hsm  = Usm + SMEM_U_FLOATS;        // [k][r]: k*4 + r
    ull*   red  = (ull*)(hsm + SMEM_H_FLOATS);// [(kg*64+u)*2 + pair]
    float* bs   = (float*)(red + SMEM_R_FLOATS / 2);
    float* its  = bs + SU;

    const int tid = threadIdx.x;
    const int g   = blockIdx.x >> 3;   // batch group 0..15
    const int s   = blockIdx.x & 7;    // unit slice 0..7
    const int u0  = s * SU;

    // ---- one-time setup ----
    // U slice transposed into smem: read coalesced (lanes over u), write [u][k]
    for (int i = tid; i < SU * KDIM; i += REC_THREADS) {
        int k = i >> 6, uu = i & 63;
        Usm[uu * UPAD + k] = Umat[(long)k * UNITS + u0 + uu];
    }
    if (tid < SU) {
        bs[tid]  = bvec[u0 + tid];
        its[tid] = 1.0f / tau[u0 + tid];
    }
    for (int i = tid; i < SMEM_H_FLOATS; i += REC_THREADS) hsm[i] = 0.0f;
    __syncthreads();

    // compute-phase identity
    const int u  = tid & 63;           // unit within slice
    const int kg = tid >> 6;           // k-group 0..3 (128 k each)
    const int kbase = kg * 128;
    // combine-phase identity
    const int r_ep = tid >> 6;         // row 0..3
    const int u_ep = tid & 63;         // unit within slice
    const float it_u = its[u_ep];
    const float b_u  = bs[u_ep];
    const int  hsel  = r_ep >> 1;      // which f32x2 pair
    const bool hi    = r_ep & 1;       // which half of the pair

    float* optr = out + ((long)(g * GROWS + r_ep) * SEQ) * UNITS + u0 + u_ep;
    float* hbuf_g0 = &g_hbuf_t[0][g][0][0];
    float* hbuf_g1 = &g_hbuf_t[1][g][0][0];

    // prefetch xw for t = 0
    float xw = __ldcg(optr);

    for (int t = 0; t < SEQ; ++t) {
        // ---- compute partial dots over k in [kbase, kbase+128) ----
        ull a0 = 0ull, a1 = 0ull, a2 = 0ull, a3 = 0ull;
        const float* Urow = Usm + u * UPAD + kbase;
        const float* Hrow = hsm + kbase * 4;
#pragma unroll 8
        for (int kk = 0; kk < 128; kk += 4) {
            float4 uv = *(const float4*)(Urow + kk);
            ulonglong2 h0 = *(const ulonglong2*)(Hrow + (kk + 0) * 4);
            ulonglong2 h1 = *(const ulonglong2*)(Hrow + (kk + 1) * 4);
            ulonglong2 h2 = *(const ulonglong2*)(Hrow + (kk + 2) * 4);
            ulonglong2 h3 = *(const ulonglong2*)(Hrow + (kk + 3) * 4);
            ull p0 = pack2(uv.x), p1 = pack2(uv.y);
            ull p2 = pack2(uv.z), p3 = pack2(uv.w);
            a0 = fma2(h0.x, p0, a0);  a1 = fma2(h0.y, p0, a1);
            a2 = fma2(h1.x, p1, a2);  a3 = fma2(h1.y, p1, a3);
            a0 = fma2(h2.x, p2, a0);  a1 = fma2(h2.y, p2, a1);
            a2 = fma2(h3.x, p3, a2);  a3 = fma2(h3.y, p3, a3);
        }
        red[(kg * SU + u) * 2 + 0] = add2(a0, a2);   // rows (0,1)
        red[(kg * SU + u) * 2 + 1] = add2(a1, a3);   // rows (2,3)
        __syncthreads();

        // ---- combine + LTC update ----
        {
            float dot = 0.0f;
#pragma unroll
            for (int q = 0; q < 4; q++) {
                ull v = red[(q * SU + u_ep) * 2 + hsel];
                float2 f = *(float2*)&v;
                dot += hi ? f.y : f.x;
            }
            const float hp = hsm[(u0 + u_ep) * 4 + r_ep];
            const float hn = hp + it_u * (xw + dot + b_u - hp);
            *optr = hn;
            optr += UNITS;
            // write h slice (transposed layout) into next buffer
            float* hb = ((t + 1) & 1) ? hbuf_g1 : hbuf_g0;
            hb[(u0 + u_ep) * 4 + r_ep] = hn;
            // prefetch next xw (hidden behind barrier + next compute)
            if (t + 1 < SEQ) xw = __ldcg(optr);
        }

        // ---- cluster step barrier (release/acquire; also a block sync) ----
        asm volatile("barrier.cluster.arrive.aligned;" ::: "memory");
        asm volatile("barrier.cluster.wait.aligned;"   ::: "memory");

        // ---- reload full group h for step t+1 ----
        if (t + 1 < SEQ) {
            const float4* src =
                (const float4*)(((t + 1) & 1) ? hbuf_g1 : hbuf_g0);
            float4* dst = (float4*)hsm;
#pragma unroll
            for (int i = 0; i < SMEM_H_FLOATS / 4; i += REC_THREADS)
                dst[i + tid] = __ldcg(src + i + tid);
            __syncthreads();
        }
    }
}

// ---------------------------------------------------------------------------
// Launch
// ---------------------------------------------------------------------------
extern "C" void kernel_launch(void* const* d_in, const int* in_sizes, int n_in,
                              void* d_out, int out_size) {
    (void)in_sizes; (void)n_in; (void)out_size;
    const float* x   = (const float*)d_in[0];   // [64,1024,256]
    const float* W   = (const float*)d_in[1];   // [256,512]
    const float* U   = (const float*)d_in[2];   // [512,512]
    const float* b   = (const float*)d_in[3];   // [512]
    const float* tau = (const float*)d_in[4];   // [512]
    float* out = (float*)d_out;                 // [64,1024,512]

    // 1) xW -> out
    dim3 ggrid(UNITS / BN, (BATCH * SEQ) / BM);  // (4, 512)
    ltc_xw_gemm<<<ggrid, 256>>>(x, W, out);

    // 2) persistent cluster-synced recurrence (~142 KB dynamic smem)
    cudaFuncSetAttribute(ltc_recur, cudaFuncAttributeMaxDynamicSharedMemorySize,
                         SMEM_BYTES);
    ltc_recur<<<NGRP * NSLICE, REC_THREADS, SMEM_BYTES>>>(U, b, tau, out);
}

// round 11
// speedup vs baseline: 1.3895x; 1.3895x over previous
#include <cuda_runtime.h>
#include <cuda_bf16.h>

// Problem constants
#define BATCH 64
#define SEQ   1024
#define DIN   256
#define UNITS 512

// Recurrence partitioning: 16 batch-groups x 8 unit-slices = 128 CTAs.
// One group == one 8-CTA cluster -> HW cluster barrier for the step sync.
#define NGRP   16     // batch groups
#define GROWS  4      // batch rows per group
#define NSLICE 8      // unit slices per group (cluster size)
#define SU     64     // units per slice
#define KDIM   512    // contraction dim (= UNITS)

typedef unsigned long long ull;

// Double-buffered hidden state, transposed per group: [buf][g][k][r]
__device__ float g_hbuf_t[2][NGRP][KDIM][GROWS];   // 256 KB

// ---------------------------------------------------------------------------
// f32x2 packed helpers (FFMA2 path — only reachable via PTX)
// ---------------------------------------------------------------------------
__device__ __forceinline__ ull pack2(float v) {
    ull d; asm("mov.b64 %0, {%1, %1};" : "=l"(d) : "f"(v)); return d;
}
__device__ __forceinline__ ull packpair(float a, float b) {
    ull d; asm("mov.b64 %0, {%1, %2};" : "=l"(d) : "f"(a), "f"(b)); return d;
}
__device__ __forceinline__ ull fma2(ull a, ull b, ull c) {
    ull d; asm("fma.rn.f32x2 %0, %1, %2, %3;" : "=l"(d) : "l"(a), "l"(b), "l"(c)); return d;
}
__device__ __forceinline__ ull add2(ull a, ull b) {
    ull d; asm("add.rn.f32x2 %0, %1, %2;" : "=l"(d) : "l"(a), "l"(b)); return d;
}
__device__ __forceinline__ float2 unpack2(ull v) {
    float2 f; asm("mov.b64 {%0, %1}, %2;" : "=f"(f.x), "=f"(f.y) : "l"(v)); return f;
}

// ---------------------------------------------------------------------------
// Kernel 1: xW GEMM  C[65536,512] = A[65536,256] @ B[256,512]  (unchanged)
// ---------------------------------------------------------------------------
#define BM 128
#define BN 128
#define BK 8

__global__ __launch_bounds__(256) void ltc_xw_gemm(
    const float* __restrict__ A, const float* __restrict__ B,
    float* __restrict__ C)
{
    __shared__ float Asm[BK][BM];
    __shared__ float Bsm[BK][BN];

    const int tid = threadIdx.x;
    const int bm = blockIdx.y * BM;
    const int bn = blockIdx.x * BN;
    const int tx = tid & 15;
    const int ty = tid >> 4;
    const int arow = tid >> 1;
    const int acol = (tid & 1) * 4;
    const int brow = tid >> 5;
    const int bcol = (tid & 31) * 4;

    const float* Ap = A + (long)(bm + arow) * DIN + acol;
    const float* Bp = B + (long)brow * UNITS + bn + bcol;

    float acc[8][8];
#pragma unroll
    for (int i = 0; i < 8; i++)
#pragma unroll
        for (int j = 0; j < 8; j++) acc[i][j] = 0.0f;

    for (int k0 = 0; k0 < DIN; k0 += BK) {
        float4 av = *(const float4*)(Ap + k0);
        float4 bv = *(const float4*)(Bp + (long)k0 * UNITS);
        __syncthreads();
        Asm[acol + 0][arow] = av.x;
        Asm[acol + 1][arow] = av.y;
        Asm[acol + 2][arow] = av.z;
        Asm[acol + 3][arow] = av.w;
        *(float4*)&Bsm[brow][bcol] = bv;
        __syncthreads();
#pragma unroll
        for (int k = 0; k < BK; ++k) {
            float a[8], b[8];
            *(float4*)(a)     = *(const float4*)&Asm[k][ty * 8];
            *(float4*)(a + 4) = *(const float4*)&Asm[k][ty * 8 + 4];
            *(float4*)(b)     = *(const float4*)&Bsm[k][tx * 8];
            *(float4*)(b + 4) = *(const float4*)&Bsm[k][tx * 8 + 4];
#pragma unroll
            for (int i = 0; i < 8; i++)
#pragma unroll
                for (int j = 0; j < 8; j++)
                    acc[i][j] = fmaf(a[i], b[j], acc[i][j]);
        }
    }
#pragma unroll
    for (int i = 0; i < 8; i++) {
        float* crow = C + (long)(bm + ty * 8 + i) * UNITS + bn + tx * 8;
        *(float4*)(crow)     = make_float4(acc[i][0], acc[i][1], acc[i][2], acc[i][3]);
        *(float4*)(crow + 4) = make_float4(acc[i][4], acc[i][5], acc[i][6], acc[i][7]);
    }
}

// ---------------------------------------------------------------------------
// Kernel 2: persistent LTC recurrence — U resident in REGISTERS.
//
// Grid = 128 CTAs, __cluster_dims__(8): blockIdx.x = g*8 + s.
// Cluster g owns rows [4g,4g+4); CTA s owns units [64s,64s+64).
// Compute thread (U4 = tid&15 -> units 4*U4..4*U4+3, kg = tid>>4 -> 32 k):
//   holds its 32x4 U sub-block in 64 packed f32x2 registers (128 regs),
//   inner loop = broadcast LDS.128 of h[k][0..3] + 8 fma.rn.f32x2.
// Combine thread (r = tid>>6, u = tid&63): tree-sums 16 k-group partials,
//   applies the LTC update with the xw value prefetched last step, writes
//   out + the transposed global h double-buffer.
// Step sync: one barrier.cluster (release/acquire) + 8 KB h reload from L2.
// ---------------------------------------------------------------------------
#define REC_THREADS 256

__global__ __launch_bounds__(REC_THREADS, 1) __cluster_dims__(NSLICE, 1, 1)
void ltc_recur(
    const float* __restrict__ Umat,  // [512, 512] row-major [k][u]
    const float* __restrict__ bvec,  // [512]
    const float* __restrict__ tau,   // [512]
    float* __restrict__ out)         // [64, 1024, 512]; holds xW on entry
{
    __shared__ float hsm[KDIM * GROWS];          // [k][r]  8 KB
    __shared__ ull   red[16 * GROWS * (SU / 2)]; // [kg][r][u_pair]  16 KB

    const int tid = threadIdx.x;
    const int g   = blockIdx.x >> 3;   // batch group 0..15
    const int s   = blockIdx.x & 7;    // unit slice 0..7
    const int u0  = s * SU;

    // compute-phase identity
    const int U4 = tid & 15;           // unit quad 0..15
    const int u4 = U4 * 4;             // first unit of quad
    const int kg = tid >> 4;           // k-group 0..15 (32 k each)
    const int kbase = kg * 32;

    // combine-phase identity
    const int r_ep = tid >> 6;         // row 0..3
    const int u_ep = tid & 63;         // unit within slice

    // ---- one-time setup ----
    // U sub-block into registers, packed as f32x2 unit-pairs: Ur[k][pair]
    ull Ur[32][2];
    {
        const float* Ub = Umat + (long)kbase * UNITS + u0 + u4;
#pragma unroll
        for (int kk = 0; kk < 32; kk++) {
            float4 v = *(const float4*)(Ub + (long)kk * UNITS);
            Ur[kk][0] = packpair(v.x, v.y);
            Ur[kk][1] = packpair(v.z, v.w);
        }
    }
    const float it_u = 1.0f / tau[u0 + u_ep];
    const float b_u  = bvec[u0 + u_ep];

    for (int i = tid; i < KDIM * GROWS; i += REC_THREADS) hsm[i] = 0.0f;
    __syncthreads();

    float* optr = out + ((long)(g * GROWS + r_ep) * SEQ) * UNITS + u0 + u_ep;
    float* hb0 = &g_hbuf_t[0][g][0][0];
    float* hb1 = &g_hbuf_t[1][g][0][0];
    const int hidx = (u0 + u_ep) * GROWS + r_ep;

    // prefetch xw for t = 0
    float xw = __ldcg(optr);

    for (int t = 0; t < SEQ; ++t) {
        // ---- compute: partial dots over this thread's 32 k, 4 units ----
        ull a00 = 0, a01 = 0, a10 = 0, a11 = 0;
        ull a20 = 0, a21 = 0, a30 = 0, a31 = 0;
        const float* Hrow = hsm + kbase * GROWS;
#pragma unroll
        for (int kk = 0; kk < 32; kk++) {
            float4 hv = *(const float4*)(Hrow + kk * GROWS);  // broadcast
            ull h0 = pack2(hv.x), h1 = pack2(hv.y);
            ull h2 = pack2(hv.z), h3 = pack2(hv.w);
            a00 = fma2(Ur[kk][0], h0, a00);  a01 = fma2(Ur[kk][1], h0, a01);
            a10 = fma2(Ur[kk][0], h1, a10);  a11 = fma2(Ur[kk][1], h1, a11);
            a20 = fma2(Ur[kk][0], h2, a20);  a21 = fma2(Ur[kk][1], h2, a21);
            a30 = fma2(Ur[kk][0], h3, a30);  a31 = fma2(Ur[kk][1], h3, a31);
        }
        // red[kg][r][pair]: pair index = 2*U4 + p
        {
            ull* rb = red + kg * (GROWS * (SU / 2)) + 2 * U4;
            rb[0 * (SU / 2) + 0] = a00;  rb[0 * (SU / 2) + 1] = a01;
            rb[1 * (SU / 2) + 0] = a10;  rb[1 * (SU / 2) + 1] = a11;
            rb[2 * (SU / 2) + 0] = a20;  rb[2 * (SU / 2) + 1] = a21;
            rb[3 * (SU / 2) + 0] = a30;  rb[3 * (SU / 2) + 1] = a31;
        }
        __syncthreads();

        // ---- combine + LTC update (thread -> (r_ep, u_ep)) ----
        {
            const ull* rp = red + r_ep * (SU / 2) + (u_ep >> 1);
            ull v[16];
#pragma unroll
            for (int q = 0; q < 16; q++)
                v[q] = rp[q * (GROWS * (SU / 2))];
#pragma unroll
            for (int st = 8; st >= 1; st >>= 1)
#pragma unroll
                for (int q = 0; q < st; q++)
                    v[q] = add2(v[q], v[q + st]);
            float2 f = unpack2(v[0]);
            const float dot = (u_ep & 1) ? f.y : f.x;

            const float hp = hsm[hidx];
            const float hn = hp + it_u * (xw + dot + b_u - hp);
            *optr = hn;
            optr += UNITS;
            float* hb = ((t + 1) & 1) ? hb1 : hb0;
            hb[hidx] = hn;
            if (t + 1 < SEQ) xw = __ldcg(optr);   // prefetch next xw
        }

        // ---- cluster step barrier + h reload for step t+1 ----
        if (t + 1 < SEQ) {
            asm volatile("barrier.cluster.arrive.aligned;" ::: "memory");
            asm volatile("barrier.cluster.wait.aligned;"   ::: "memory");

            const float4* s4 =
                (const float4*)(((t + 1) & 1) ? hb1 : hb0);
            float4* d4 = (float4*)hsm;
            d4[tid]       = __ldcg(s4 + tid);
            d4[tid + 256] = __ldcg(s4 + tid + 256);
            __syncthreads();
        }
    }
}

// ---------------------------------------------------------------------------
// Launch
// ---------------------------------------------------------------------------
extern "C" void kernel_launch(void* const* d_in, const int* in_sizes, int n_in,
                              void* d_out, int out_size) {
    (void)in_sizes; (void)n_in; (void)out_size;
    const float* x   = (const float*)d_in[0];   // [64,1024,256]
    const float* W   = (const float*)d_in[1];   // [256,512]
    const float* U   = (const float*)d_in[2];   // [512,512]
    const float* b   = (const float*)d_in[3];   // [512]
    const float* tau = (const float*)d_in[4];   // [512]
    float* out = (float*)d_out;                 // [64,1024,512]

    // 1) xW -> out
    dim3 ggrid(UNITS / BN, (BATCH * SEQ) / BM);  // (4, 512)
    ltc_xw_gemm<<<ggrid, 256>>>(x, W, out);

    // 2) persistent cluster-synced recurrence, U in registers
    ltc_recur<<<NGRP * NSLICE, REC_THREADS>>>(U, b, tau, out);
}